// round 3
// baseline (speedup 1.0000x reference)
#include <cuda_runtime.h>
#include <cuda_bf16.h>
#include <cstdint>

// ---------------------------------------------------------------------------
// Problem constants
// ---------------------------------------------------------------------------
#define LQ      22223
#define CDIM    256
#define NHEADS  8
#define NLVL    4
#define NPTS    4
#define KDIM    256

// Level spatial shapes and starts
__device__ __constant__ int c_H[NLVL]     = {100, 50, 25, 13};
__device__ __constant__ int c_W[NLVL]     = {167, 84, 42, 21};
__device__ __constant__ int c_start[NLVL] = {0, 16700, 20900, 21950};

// ---------------------------------------------------------------------------
// Scratch (device globals; no allocation allowed)
// ---------------------------------------------------------------------------
__device__ float g_v    [LQ * CDIM];   // value @ W_val + b_val
__device__ float g_off  [LQ * CDIM];   // query @ W_off + b_off
__device__ float g_attn [LQ * 128];    // attn logits (softmax fused into sampling)
__device__ float g_mid  [LQ * CDIM];   // sampled+weighted output, pre-W_out

__device__ __nv_bfloat16 g_ah[LQ * KDIM];    // A split hi
__device__ __nv_bfloat16 g_al[LQ * KDIM];    // A split lo

// Weight splits, transposed to [N,K], packed: WVAL | WOFF | WATTN | WOUT
#define W_VAL_OFF   0
#define W_OFF_OFF   (256 * 256)
#define W_ATTN_OFF  (2 * 256 * 256)
#define W_OUT_OFF   (2 * 256 * 256 + 128 * 256)
#define W_TOTAL     (3 * 256 * 256 + 128 * 256)
__device__ __nv_bfloat16 g_wh[W_TOTAL];
__device__ __nv_bfloat16 g_wl[W_TOTAL];

// ---------------------------------------------------------------------------
// mma.sync / ldmatrix helpers (plain sm_103 — no 'a'-suffix features)
// ---------------------------------------------------------------------------
__device__ __forceinline__ uint32_t smem_u32(const void* p) {
    uint32_t a;
    asm("{ .reg .u64 t; cvta.to.shared.u64 t, %1; cvt.u32.u64 %0, t; }"
        : "=r"(a) : "l"(p));
    return a;
}
__device__ __forceinline__ void ldsm_x4(uint32_t* r, uint32_t addr) {
    asm volatile("ldmatrix.sync.aligned.m8n8.x4.shared.b16 {%0,%1,%2,%3}, [%4];"
                 : "=r"(r[0]), "=r"(r[1]), "=r"(r[2]), "=r"(r[3]) : "r"(addr));
}
__device__ __forceinline__ void mma_bf16(float* d, const uint32_t* a,
                                         const uint32_t* b) {
    asm volatile(
        "mma.sync.aligned.m16n8k16.row.col.f32.bf16.bf16.f32 "
        "{%0,%1,%2,%3}, {%4,%5,%6,%7}, {%8,%9}, {%0,%1,%2,%3};"
        : "+f"(d[0]), "+f"(d[1]), "+f"(d[2]), "+f"(d[3])
        : "r"(a[0]), "r"(a[1]), "r"(a[2]), "r"(a[3]), "r"(b[0]), "r"(b[1]));
}

// ---------------------------------------------------------------------------
// Prep kernels
// ---------------------------------------------------------------------------
// Split fp32 A[M,K] -> bf16 hi/lo, same layout
__global__ void split_a(const float* __restrict__ A,
                        __nv_bfloat16* __restrict__ ah,
                        __nv_bfloat16* __restrict__ al, int total)
{
    int i = blockIdx.x * blockDim.x + threadIdx.x;
    if (i >= total) return;
    float v = A[i];
    __nv_bfloat16 h = __float2bfloat16(v);
    ah[i] = h;
    al[i] = __float2bfloat16(v - __bfloat162float(h));
}

// Split fp32 W[K,N] -> bf16 hi/lo transposed to [N,K]
__global__ void prep_split_w(const float* __restrict__ W,
                             __nv_bfloat16* __restrict__ bt_hi,
                             __nv_bfloat16* __restrict__ bt_lo,
                             int N, int total)
{
    int idx = blockIdx.x * blockDim.x + threadIdx.x;
    if (idx >= total) return;
    int k = idx / N;
    int n = idx - k * N;
    float a = W[idx];
    __nv_bfloat16 hi = __float2bfloat16(a);
    __nv_bfloat16 lo = __float2bfloat16(a - __bfloat162float(hi));
    bt_hi[(size_t)n * KDIM + k] = hi;
    bt_lo[(size_t)n * KDIM + k] = lo;
}

// ---------------------------------------------------------------------------
// bf16 mma.sync GEMM with split-bf16 3-pass accumulation.
// C[M,N] = A[M,256] @ B[256,N] + bias   (B given as [N,K] hi/lo)
// BM=128, BN=64, BK=64, 256 threads (8 warps), warp tile 32x32.
// ---------------------------------------------------------------------------
#define LDT 72   // SMEM row stride in bf16 elems (64 data + 8 pad)

__global__ __launch_bounds__(256)
void gemm_mma(const __nv_bfloat16* __restrict__ ah,
              const __nv_bfloat16* __restrict__ al,
              const __nv_bfloat16* __restrict__ bh,
              const __nv_bfloat16* __restrict__ bl,
              const float* __restrict__ bias,
              float* __restrict__ C,
              int M, int N)
{
    __shared__ __nv_bfloat16 As[128 * LDT];
    __shared__ __nv_bfloat16 Bs[64 * LDT];

    const int tid  = threadIdx.x;
    const int wid  = tid >> 5;
    const int lane = tid & 31;
    const int m0   = blockIdx.x * 128;
    const int col0 = blockIdx.y * 64;
    const int warp_m = wid & 3;     // 0..3 -> 32 rows each
    const int warp_n = wid >> 2;    // 0..1 -> 32 cols each

    const uint32_t sA = smem_u32(As);
    const uint32_t sB = smem_u32(Bs);

    float acc[2][4][4];
    #pragma unroll
    for (int i = 0; i < 2; i++)
        #pragma unroll
        for (int j = 0; j < 4; j++)
            #pragma unroll
            for (int k = 0; k < 4; k++) acc[i][j][k] = 0.0f;

    // Precomputed ldmatrix SMEM addresses (depend only on lane/warp)
    const int a_row  = warp_m * 32 + (lane & 15);
    const int a_colb = (lane >> 4) << 3;
    const int b_row  = warp_n * 32 + (lane & 7) + ((lane >> 4) << 3);
    const int b_colb = ((lane >> 3) & 1) << 3;

    #pragma unroll 1
    for (int it = 0; it < 12; ++it) {
        const int pass = it >> 2;
        const int k0   = (it & 3) << 6;
        const __nv_bfloat16* Ap = (pass == 2) ? al : ah;
        const __nv_bfloat16* Bp = (pass == 1) ? bl : bh;

        // load A tile: 128 x 64
        #pragma unroll
        for (int i = 0; i < 4; i++) {
            const int e  = tid + (i << 8);
            const int r  = e >> 3;
            const int c8 = (e & 7) << 3;
            uint4 v = make_uint4(0, 0, 0, 0);
            const int gr = m0 + r;
            if (gr < M)
                v = *reinterpret_cast<const uint4*>(&Ap[(size_t)gr * KDIM + k0 + c8]);
            *reinterpret_cast<uint4*>(&As[r * LDT + c8]) = v;
        }
        // load B tile: 64 x 64
        #pragma unroll
        for (int i = 0; i < 2; i++) {
            const int e  = tid + (i << 8);
            const int r  = e >> 3;
            const int c8 = (e & 7) << 3;
            uint4 v = *reinterpret_cast<const uint4*>(
                &Bp[(size_t)(col0 + r) * KDIM + k0 + c8]);
            *reinterpret_cast<uint4*>(&Bs[r * LDT + c8]) = v;
        }
        __syncthreads();

        #pragma unroll
        for (int kk = 0; kk < 64; kk += 16) {
            uint32_t afr[2][4], bfr[2][4];
            #pragma unroll
            for (int mt = 0; mt < 2; mt++) {
                const uint32_t addr =
                    sA + (uint32_t)(((a_row + mt * 16) * LDT + kk + a_colb) * 2);
                ldsm_x4(afr[mt], addr);
            }
            #pragma unroll
            for (int np = 0; np < 2; np++) {
                const uint32_t addr =
                    sB + (uint32_t)(((b_row + np * 16) * LDT + kk + b_colb) * 2);
                ldsm_x4(bfr[np], addr);
            }
            #pragma unroll
            for (int mt = 0; mt < 2; mt++)
                #pragma unroll
                for (int nt = 0; nt < 4; nt++)
                    mma_bf16(acc[mt][nt], afr[mt], &bfr[nt >> 1][(nt & 1) * 2]);
        }
        __syncthreads();
    }

    // Epilogue: thread i of mma tile holds (m=i/4, n=2*(i%4)) and (m+8, .)
    const int er = lane >> 2;
    const int ec = (lane & 3) << 1;
    #pragma unroll
    for (int mt = 0; mt < 2; mt++) {
        #pragma unroll
        for (int nt = 0; nt < 4; nt++) {
            const int col = col0 + warp_n * 32 + nt * 8 + ec;
            const float b0 = bias[col], b1 = bias[col + 1];
            const int r0 = m0 + warp_m * 32 + mt * 16 + er;
            if (r0 < M) {
                float2 o = make_float2(acc[mt][nt][0] + b0, acc[mt][nt][1] + b1);
                *reinterpret_cast<float2*>(&C[(size_t)r0 * N + col]) = o;
            }
            if (r0 + 8 < M) {
                float2 o = make_float2(acc[mt][nt][2] + b0, acc[mt][nt][3] + b1);
                *reinterpret_cast<float2*>(&C[(size_t)(r0 + 8) * N + col]) = o;
            }
        }
    }
}

// ---------------------------------------------------------------------------
// Deformable sampling with fused softmax: one warp per (q, head), lane=channel.
// ---------------------------------------------------------------------------
__global__ __launch_bounds__(256) void sample_kernel(
    const float* __restrict__ v, const float* __restrict__ off,
    const float* __restrict__ logits, const float* __restrict__ ref,
    float* __restrict__ mid)
{
    const int q    = blockIdx.x;
    const int h    = threadIdx.x >> 5;
    const int lane = threadIdx.x & 31;

    // ---- fused softmax over the 16 logits of (q,h) ----
    float lg = logits[(size_t)q * 128 + h * 16 + (lane & 15)];
    float mx = lg;
    #pragma unroll
    for (int m = 8; m; m >>= 1) mx = fmaxf(mx, __shfl_xor_sync(~0u, mx, m));
    float ex = __expf(lg - mx);
    float sm = ex;
    #pragma unroll
    for (int m = 8; m; m >>= 1) sm += __shfl_xor_sync(~0u, sm, m);
    const float wn = ex / sm;   // normalized weight held by lane (lane&15)

    const float* offq = off + (size_t)q * CDIM + h * 32;
    const float* refq = ref + (size_t)q * 16;

    float acc = 0.0f;

    #pragma unroll
    for (int l = 0; l < NLVL; l++) {
        const float cx = refq[l * 4 + 0];
        const float cy = refq[l * 4 + 1];
        const float rw = refq[l * 4 + 2];
        const float rh = refq[l * 4 + 3];
        const int H = c_H[l], W = c_W[l];
        const int start = c_start[l];
        const float* vbase = v + ((size_t)start * CDIM) + h * 32 + lane;

        #pragma unroll
        for (int p = 0; p < NPTS; p++) {
            const float ox = offq[l * 8 + p * 2 + 0];
            const float oy = offq[l * 8 + p * 2 + 1];
            const float x = (cx + ox * 0.125f * rw) * (float)W - 0.5f;
            const float y = (cy + oy * 0.125f * rh) * (float)H - 0.5f;

            const float x0f = floorf(x), y0f = floorf(y);
            const int x0 = (int)x0f, y0 = (int)y0f;
            const float wx1 = x - x0f, wy1 = y - y0f;
            const float wx0 = 1.0f - wx1, wy0 = 1.0f - wy1;

            const bool vx0 = (x0 >= 0) && (x0 < W);
            const bool vx1 = (x0 + 1 >= 0) && (x0 + 1 < W);
            const bool vy0 = (y0 >= 0) && (y0 < H);
            const bool vy1 = (y0 + 1 >= 0) && (y0 + 1 < H);

            float s = 0.0f;
            if (vy0) {
                const float* rowp = vbase + (size_t)y0 * W * CDIM;
                if (vx0) s = fmaf(wy0 * wx0, rowp[(size_t)x0 * CDIM], s);
                if (vx1) s = fmaf(wy0 * wx1, rowp[(size_t)(x0 + 1) * CDIM], s);
            }
            if (vy1) {
                const float* rowp = vbase + (size_t)(y0 + 1) * W * CDIM;
                if (vx0) s = fmaf(wy1 * wx0, rowp[(size_t)x0 * CDIM], s);
                if (vx1) s = fmaf(wy1 * wx1, rowp[(size_t)(x0 + 1) * CDIM], s);
            }
            const float aw = __shfl_sync(~0u, wn, (l * 4 + p) | (lane & 16));
            acc = fmaf(aw, s, acc);
        }
    }

    mid[(size_t)q * CDIM + h * 32 + lane] = acc;
}

// ---------------------------------------------------------------------------
// Launch
// ---------------------------------------------------------------------------
extern "C" void kernel_launch(void* const* d_in, const int* in_sizes, int n_in,
                              void* d_out, int out_size)
{
    const float* query  = (const float*)d_in[0];
    const float* ref    = (const float*)d_in[1];
    const float* value  = (const float*)d_in[2];
    const float* W_off  = (const float*)d_in[3];
    const float* b_off  = (const float*)d_in[4];
    const float* W_attn = (const float*)d_in[5];
    const float* b_attn = (const float*)d_in[6];
    const float* W_val  = (const float*)d_in[7];
    const float* b_val  = (const float*)d_in[8];
    const float* W_out  = (const float*)d_in[9];
    const float* b_out  = (const float*)d_in[10];
    float* out = (float*)d_out;

    float *gv, *goff, *gattn, *gmid;
    __nv_bfloat16 *ah, *al, *wh, *wl;
    cudaGetSymbolAddress((void**)&gv,    g_v);
    cudaGetSymbolAddress((void**)&goff,  g_off);
    cudaGetSymbolAddress((void**)&gattn, g_attn);
    cudaGetSymbolAddress((void**)&gmid,  g_mid);
    cudaGetSymbolAddress((void**)&ah,    g_ah);
    cudaGetSymbolAddress((void**)&al,    g_al);
    cudaGetSymbolAddress((void**)&wh,    g_wh);
    cudaGetSymbolAddress((void**)&wl,    g_wl);

    const int MT = (LQ + 127) / 128;   // 174
    dim3 g256(MT, 4);
    dim3 g128(MT, 2);
    const int AT = LQ * KDIM;          // A elements

    // Weight prep (all four up front)
    prep_split_w<<<(256 * 256 + 255) / 256, 256>>>(W_val,  wh + W_VAL_OFF,  wl + W_VAL_OFF,  256, 256 * 256);
    prep_split_w<<<(256 * 256 + 255) / 256, 256>>>(W_off,  wh + W_OFF_OFF,  wl + W_OFF_OFF,  256, 256 * 256);
    prep_split_w<<<(256 * 128 + 255) / 256, 256>>>(W_attn, wh + W_ATTN_OFF, wl + W_ATTN_OFF, 128, 256 * 128);
    prep_split_w<<<(256 * 256 + 255) / 256, 256>>>(W_out,  wh + W_OUT_OFF,  wl + W_OUT_OFF,  256, 256 * 256);

    // 1. v = value @ W_val + b_val
    split_a<<<(AT + 255) / 256, 256>>>(value, ah, al, AT);
    gemm_mma<<<g256, 256>>>(ah, al, wh + W_VAL_OFF, wl + W_VAL_OFF, b_val, gv, LQ, 256);

    // 2+3. off / attn logits from query
    split_a<<<(AT + 255) / 256, 256>>>(query, ah, al, AT);
    gemm_mma<<<g256, 256>>>(ah, al, wh + W_OFF_OFF,  wl + W_OFF_OFF,  b_off,  goff,  LQ, 256);
    gemm_mma<<<g128, 256>>>(ah, al, wh + W_ATTN_OFF, wl + W_ATTN_OFF, b_attn, gattn, LQ, 128);

    // 4. sampling (softmax fused)
    sample_kernel<<<LQ, 256>>>(gv, goff, gattn, ref, gmid);

    // 5. out = mid @ W_out + b_out
    split_a<<<(AT + 255) / 256, 256>>>(gmid, ah, al, AT);
    gemm_mma<<<g256, 256>>>(ah, al, wh + W_OUT_OFF, wl + W_OUT_OFF, b_out, out, LQ, 256);
}

// round 5
// speedup vs baseline: 1.4590x; 1.4590x over previous
#include <cuda_runtime.h>
#include <cuda_bf16.h>
#include <cstdint>

// ---------------------------------------------------------------------------
// Problem constants
// ---------------------------------------------------------------------------
#define LQ      22223
#define CDIM    256
#define NHEADS  8
#define NLVL    4
#define NPTS    4
#define KDIM    256

__device__ __constant__ int c_H[NLVL]     = {100, 50, 25, 13};
__device__ __constant__ int c_W[NLVL]     = {167, 84, 42, 21};
__device__ __constant__ int c_start[NLVL] = {0, 16700, 20900, 21950};

// ---------------------------------------------------------------------------
// Scratch (device globals; no allocation allowed)
// ---------------------------------------------------------------------------
__device__ float g_v    [LQ * CDIM];
__device__ float g_off  [LQ * CDIM];
__device__ float g_attn [LQ * 128];
__device__ float g_mid  [LQ * CDIM];

// Weight splits, transposed to [N,K], packed: WVAL | WOFF | WATTN | WOUT
#define W_VAL_OFF   0
#define W_OFF_OFF   (256 * 256)
#define W_ATTN_OFF  (2 * 256 * 256)
#define W_OUT_OFF   (2 * 256 * 256 + 128 * 256)
#define W_TOTAL     (3 * 256 * 256 + 128 * 256)
__device__ __nv_bfloat16 g_wh[W_TOTAL];
__device__ __nv_bfloat16 g_wl[W_TOTAL];

// ---------------------------------------------------------------------------
// mma.sync / ldmatrix helpers (plain sm_103)
// ---------------------------------------------------------------------------
__device__ __forceinline__ uint32_t smem_u32(const void* p) {
    uint32_t a;
    asm("{ .reg .u64 t; cvta.to.shared.u64 t, %1; cvt.u32.u64 %0, t; }"
        : "=r"(a) : "l"(p));
    return a;
}
__device__ __forceinline__ void ldsm_x4(uint32_t* r, uint32_t addr) {
    asm volatile("ldmatrix.sync.aligned.m8n8.x4.shared.b16 {%0,%1,%2,%3}, [%4];"
                 : "=r"(r[0]), "=r"(r[1]), "=r"(r[2]), "=r"(r[3]) : "r"(addr));
}
__device__ __forceinline__ void mma_bf16(float* d, const uint32_t* a,
                                         const uint32_t* b) {
    asm volatile(
        "mma.sync.aligned.m16n8k16.row.col.f32.bf16.bf16.f32 "
        "{%0,%1,%2,%3}, {%4,%5,%6,%7}, {%8,%9}, {%0,%1,%2,%3};"
        : "+f"(d[0]), "+f"(d[1]), "+f"(d[2]), "+f"(d[3])
        : "r"(a[0]), "r"(a[1]), "r"(a[2]), "r"(a[3]), "r"(b[0]), "r"(b[1]));
}

// ---------------------------------------------------------------------------
// Fused weight prep: split all four fp32 W[K,N] into bf16 hi/lo at [N,K].
// Segments: W_val(256) | W_off(256) | W_attn(128) | W_out(256)
// ---------------------------------------------------------------------------
__global__ void prep_all_w(const float* __restrict__ Wv,
                           const float* __restrict__ Wo,
                           const float* __restrict__ Wa,
                           const float* __restrict__ Wu,
                           __nv_bfloat16* __restrict__ wh,
                           __nv_bfloat16* __restrict__ wl)
{
    int i = blockIdx.x * blockDim.x + threadIdx.x;
    if (i >= W_TOTAL) return;
    const float* W;
    int N, local, base;
    if (i < 65536)        { W = Wv; N = 256; base = W_VAL_OFF;  local = i; }
    else if (i < 131072)  { W = Wo; N = 256; base = W_OFF_OFF;  local = i - 65536; }
    else if (i < 163840)  { W = Wa; N = 128; base = W_ATTN_OFF; local = i - 131072; }
    else                  { W = Wu; N = 256; base = W_OUT_OFF;  local = i - 163840; }
    int k = local / N;
    int n = local - k * N;
    float a = W[(size_t)k * N + n];
    __nv_bfloat16 hi = __float2bfloat16(a);
    __nv_bfloat16 lo = __float2bfloat16(a - __bfloat162float(hi));
    wh[(size_t)base + (size_t)n * KDIM + k] = hi;
    wl[(size_t)base + (size_t)n * KDIM + k] = lo;
}

// ---------------------------------------------------------------------------
// K-resident split-bf16 mma.sync GEMM.
// C[M,N] = A_fp32[M,256] @ B[256,N] + bias  (B as [N,K] bf16 hi/lo)
// BM=128, BN=64, full K=256 in SMEM; A split to hi/lo in-kernel.
// One sync, then 384 HMMA/warp with no barriers.
// ---------------------------------------------------------------------------
#define LDK 264                       // bf16 elems per SMEM row (256 + 8 pad)
#define SM_AH 0
#define SM_AL (128 * LDK * 2)         //  67584
#define SM_BH (2 * 128 * LDK * 2)     // 135168
#define SM_BL (SM_BH + 64 * LDK * 2)  // 168960
#define SM_TOTAL (SM_BL + 64 * LDK * 2) // 202752

__global__ __launch_bounds__(256)
void gemm_kres(const float* __restrict__ A,
               const __nv_bfloat16* __restrict__ bh,
               const __nv_bfloat16* __restrict__ bl,
               const float* __restrict__ bias,
               float* __restrict__ C,
               int M, int N)
{
    extern __shared__ __align__(16) char smem[];
    __nv_bfloat16* Ah = reinterpret_cast<__nv_bfloat16*>(smem + SM_AH);
    __nv_bfloat16* Al = reinterpret_cast<__nv_bfloat16*>(smem + SM_AL);
    __nv_bfloat16* Bh = reinterpret_cast<__nv_bfloat16*>(smem + SM_BH);
    __nv_bfloat16* Bl = reinterpret_cast<__nv_bfloat16*>(smem + SM_BL);

    const int tid  = threadIdx.x;
    const int wid  = tid >> 5;
    const int lane = tid & 31;
    const int m0   = blockIdx.x * 128;
    const int col0 = blockIdx.y * 64;
    const int warp_m = wid & 3;
    const int warp_n = wid >> 2;

    // ---- load A (fp32) and split to hi/lo bf16 in SMEM ----
    {
        const int r  = tid >> 1;              // 0..127, 2 threads per row
        const int cb = (tid & 1) * 128;       // half-row base
        const int gr = m0 + r;
        #pragma unroll
        for (int j = 0; j < 32; j++) {        // 32 float4 per half-row
            const int c4 = cb + j * 4;
            float4 v = make_float4(0.f, 0.f, 0.f, 0.f);
            if (gr < M)
                v = *reinterpret_cast<const float4*>(&A[(size_t)gr * KDIM + c4]);
            __nv_bfloat162 h01 = __floats2bfloat162_rn(v.x, v.y);
            __nv_bfloat162 h23 = __floats2bfloat162_rn(v.z, v.w);
            __nv_bfloat162 l01 = __floats2bfloat162_rn(
                v.x - __bfloat162float(h01.x), v.y - __bfloat162float(h01.y));
            __nv_bfloat162 l23 = __floats2bfloat162_rn(
                v.z - __bfloat162float(h23.x), v.w - __bfloat162float(h23.y));
            const int o = r * LDK + c4;
            *reinterpret_cast<__nv_bfloat162*>(&Ah[o])     = h01;
            *reinterpret_cast<__nv_bfloat162*>(&Ah[o + 2]) = h23;
            *reinterpret_cast<__nv_bfloat162*>(&Al[o])     = l01;
            *reinterpret_cast<__nv_bfloat162*>(&Al[o + 2]) = l23;
        }
    }
    // ---- load B hi/lo (bf16 [N,K]) ----
    #pragma unroll
    for (int i = 0; i < 8; i++) {
        const int idx = tid + (i << 8);
        const int r  = idx >> 5;              // 0..63
        const int c8 = (idx & 31) << 3;       // 0..248
        const size_t g = (size_t)(col0 + r) * KDIM + c8;
        const int o = r * LDK + c8;
        *reinterpret_cast<uint4*>(&Bh[o]) = *reinterpret_cast<const uint4*>(&bh[g]);
        *reinterpret_cast<uint4*>(&Bl[o]) = *reinterpret_cast<const uint4*>(&bl[g]);
    }
    __syncthreads();

    // ---- MMA: 16 K-steps, 3 products per step, no barriers ----
    float acc[2][4][4];
    #pragma unroll
    for (int i = 0; i < 2; i++)
        #pragma unroll
        for (int j = 0; j < 4; j++)
            #pragma unroll
            for (int k = 0; k < 4; k++) acc[i][j][k] = 0.0f;

    const uint32_t sAh = smem_u32(Ah), sAl = smem_u32(Al);
    const uint32_t sBh = smem_u32(Bh), sBl = smem_u32(Bl);
    const int a_row  = warp_m * 32 + (lane & 15);
    const int a_colb = (lane >> 4) << 3;
    const int b_row  = warp_n * 32 + (lane & 7) + ((lane >> 4) << 3);
    const int b_colb = ((lane >> 3) & 1) << 3;

    #pragma unroll
    for (int ks = 0; ks < 16; ks++) {
        const int kc = ks << 4;
        uint32_t fah[2][4], fal[2][4], fbh[2][4], fbl[2][4];
        #pragma unroll
        for (int mt = 0; mt < 2; mt++) {
            const uint32_t off = (uint32_t)(((a_row + mt * 16) * LDK + kc + a_colb) * 2);
            ldsm_x4(fah[mt], sAh + off);
            ldsm_x4(fal[mt], sAl + off);
        }
        #pragma unroll
        for (int np = 0; np < 2; np++) {
            const uint32_t off = (uint32_t)(((b_row + np * 16) * LDK + kc + b_colb) * 2);
            ldsm_x4(fbh[np], sBh + off);
            ldsm_x4(fbl[np], sBl + off);
        }
        #pragma unroll
        for (int mt = 0; mt < 2; mt++)
            #pragma unroll
            for (int nt = 0; nt < 4; nt++)
                mma_bf16(acc[mt][nt], fah[mt], &fbh[nt >> 1][(nt & 1) * 2]);
        #pragma unroll
        for (int mt = 0; mt < 2; mt++)
            #pragma unroll
            for (int nt = 0; nt < 4; nt++)
                mma_bf16(acc[mt][nt], fah[mt], &fbl[nt >> 1][(nt & 1) * 2]);
        #pragma unroll
        for (int mt = 0; mt < 2; mt++)
            #pragma unroll
            for (int nt = 0; nt < 4; nt++)
                mma_bf16(acc[mt][nt], fal[mt], &fbh[nt >> 1][(nt & 1) * 2]);
    }

    // ---- epilogue ----
    const int er = lane >> 2;
    const int ec = (lane & 3) << 1;
    #pragma unroll
    for (int mt = 0; mt < 2; mt++) {
        #pragma unroll
        for (int nt = 0; nt < 4; nt++) {
            const int col = col0 + warp_n * 32 + nt * 8 + ec;
            const float b0 = bias[col], b1 = bias[col + 1];
            const int r0 = m0 + warp_m * 32 + mt * 16 + er;
            if (r0 < M) {
                float2 o = make_float2(acc[mt][nt][0] + b0, acc[mt][nt][1] + b1);
                *reinterpret_cast<float2*>(&C[(size_t)r0 * N + col]) = o;
            }
            if (r0 + 8 < M) {
                float2 o = make_float2(acc[mt][nt][2] + b0, acc[mt][nt][3] + b1);
                *reinterpret_cast<float2*>(&C[(size_t)(r0 + 8) * N + col]) = o;
            }
        }
    }
}

// ---------------------------------------------------------------------------
// Deformable sampling with fused softmax: one warp per (q, head), lane=channel.
// ---------------------------------------------------------------------------
__global__ __launch_bounds__(256) void sample_kernel(
    const float* __restrict__ v, const float* __restrict__ off,
    const float* __restrict__ logits, const float* __restrict__ ref,
    float* __restrict__ mid)
{
    const int q    = blockIdx.x;
    const int h    = threadIdx.x >> 5;
    const int lane = threadIdx.x & 31;

    float lg = logits[(size_t)q * 128 + h * 16 + (lane & 15)];
    float mx = lg;
    #pragma unroll
    for (int m = 8; m; m >>= 1) mx = fmaxf(mx, __shfl_xor_sync(~0u, mx, m));
    float ex = __expf(lg - mx);
    float sm = ex;
    #pragma unroll
    for (int m = 8; m; m >>= 1) sm += __shfl_xor_sync(~0u, sm, m);
    const float wn = ex / sm;

    const float* offq = off + (size_t)q * CDIM + h * 32;
    const float* refq = ref + (size_t)q * 16;

    float acc = 0.0f;

    #pragma unroll
    for (int l = 0; l < NLVL; l++) {
        const float cx = refq[l * 4 + 0];
        const float cy = refq[l * 4 + 1];
        const float rw = refq[l * 4 + 2];
        const float rh = refq[l * 4 + 3];
        const int H = c_H[l], W = c_W[l];
        const int start = c_start[l];
        const float* vbase = v + ((size_t)start * CDIM) + h * 32 + lane;

        #pragma unroll
        for (int p = 0; p < NPTS; p++) {
            const float ox = offq[l * 8 + p * 2 + 0];
            const float oy = offq[l * 8 + p * 2 + 1];
            const float x = (cx + ox * 0.125f * rw) * (float)W - 0.5f;
            const float y = (cy + oy * 0.125f * rh) * (float)H - 0.5f;

            const float x0f = floorf(x), y0f = floorf(y);
            const int x0 = (int)x0f, y0 = (int)y0f;
            const float wx1 = x - x0f, wy1 = y - y0f;
            const float wx0 = 1.0f - wx1, wy0 = 1.0f - wy1;

            const bool vx0 = (x0 >= 0) && (x0 < W);
            const bool vx1 = (x0 + 1 >= 0) && (x0 + 1 < W);
            const bool vy0 = (y0 >= 0) && (y0 < H);
            const bool vy1 = (y0 + 1 >= 0) && (y0 + 1 < H);

            float s = 0.0f;
            if (vy0) {
                const float* rowp = vbase + (size_t)y0 * W * CDIM;
                if (vx0) s = fmaf(wy0 * wx0, rowp[(size_t)x0 * CDIM], s);
                if (vx1) s = fmaf(wy0 * wx1, rowp[(size_t)(x0 + 1) * CDIM], s);
            }
            if (vy1) {
                const float* rowp = vbase + (size_t)(y0 + 1) * W * CDIM;
                if (vx0) s = fmaf(wy1 * wx0, rowp[(size_t)x0 * CDIM], s);
                if (vx1) s = fmaf(wy1 * wx1, rowp[(size_t)(x0 + 1) * CDIM], s);
            }
            const float aw = __shfl_sync(~0u, wn, (l * 4 + p) | (lane & 16));
            acc = fmaf(aw, s, acc);
        }
    }

    mid[(size_t)q * CDIM + h * 32 + lane] = acc;
}

// ---------------------------------------------------------------------------
// Launch
// ---------------------------------------------------------------------------
extern "C" void kernel_launch(void* const* d_in, const int* in_sizes, int n_in,
                              void* d_out, int out_size)
{
    const float* query  = (const float*)d_in[0];
    const float* ref    = (const float*)d_in[1];
    const float* value  = (const float*)d_in[2];
    const float* W_off  = (const float*)d_in[3];
    const float* b_off  = (const float*)d_in[4];
    const float* W_attn = (const float*)d_in[5];
    const float* b_attn = (const float*)d_in[6];
    const float* W_val  = (const float*)d_in[7];
    const float* b_val  = (const float*)d_in[8];
    const float* W_out  = (const float*)d_in[9];
    const float* b_out  = (const float*)d_in[10];
    float* out = (float*)d_out;

    float *gv, *goff, *gattn, *gmid;
    __nv_bfloat16 *wh, *wl;
    cudaGetSymbolAddress((void**)&gv,    g_v);
    cudaGetSymbolAddress((void**)&goff,  g_off);
    cudaGetSymbolAddress((void**)&gattn, g_attn);
    cudaGetSymbolAddress((void**)&gmid,  g_mid);
    cudaGetSymbolAddress((void**)&wh,    g_wh);
    cudaGetSymbolAddress((void**)&wl,    g_wl);

    cudaFuncSetAttribute(gemm_kres, cudaFuncAttributeMaxDynamicSharedMemorySize,
                         SM_TOTAL);

    const int MT = (LQ + 127) / 128;   // 174
    dim3 g256(MT, 4);
    dim3 g128(MT, 2);

    // 0. weight prep (single fused launch)
    prep_all_w<<<(W_TOTAL + 255) / 256, 256>>>(W_val, W_off, W_attn, W_out, wh, wl);

    // 1. v = value @ W_val + b_val
    gemm_kres<<<g256, 256, SM_TOTAL>>>(value, wh + W_VAL_OFF, wl + W_VAL_OFF,
                                       b_val, gv, LQ, 256);
    // 2. off = query @ W_off + b_off
    gemm_kres<<<g256, 256, SM_TOTAL>>>(query, wh + W_OFF_OFF, wl + W_OFF_OFF,
                                       b_off, goff, LQ, 256);
    // 3. attn logits = query @ W_attn + b_attn
    gemm_kres<<<g128, 256, SM_TOTAL>>>(query, wh + W_ATTN_OFF, wl + W_ATTN_OFF,
                                       b_attn, gattn, LQ, 128);
    // 4. sampling (softmax fused)
    sample_kernel<<<LQ, 256>>>(gv, goff, gattn, ref, gmid);
    // 5. out = mid @ W_out + b_out
    gemm_kres<<<g256, 256, SM_TOTAL>>>(gmid, wh + W_OUT_OFF, wl + W_OUT_OFF,
                                       b_out, out, LQ, 256);
}